// round 14
// baseline (speedup 1.0000x reference)
#include <cuda_runtime.h>
#include <cuda_bf16.h>
#include <mma.h>
#include <math.h>

using namespace nvcuda;

#define VOCAB 32000
#define EMBED 512
#define HID   1024      // DEC_H
#define SEQL  64
#define BATCH 32
#define G4    4096
#define GRID  148
#define TPB   512
#define PAD   8

#define T_ENC 64        // G4/64 tiles
#define T_DEC 64
#define T_CMB 16        // HID/64
#define T_OUT 500       // VOCAB/64

#define CH    128                      // K rows per pipeline chunk
#define BLD   72                       // padded chunk ld (LDSM bank-safe)
#define SLOTSZ (CH * BLD)              // 9216 elems = 18432 B

#define SA_BYTES 131584                // 32 * (2048+8) * 2
#define SB_BYTES (4 * SLOTSZ * 2)      // 73728 (4 slots: 2 per ks-group)
#define SC_BYTES (2 * 32 * 64 * 4)     // 16384 (2 k-split slabs)
#define SMEM_DYN (SA_BYTES + SB_BYTES + SC_BYTES)   // 221696

typedef __nv_bfloat16 bf16;

// ---------------- device scratch ----------------
__device__ bf16  d_Eenc[SEQL * BATCH * EMBED];        // [t][b][e] bf16
__device__ bf16  d_enc_outs[BATCH * SEQL * HID];      // [b][t][d] bf16
__device__ bf16  d_gb0[BATCH * HID], d_gb1[BATCH * HID];
__device__ float d_ce[BATCH * HID];
__device__ bf16  d_hb0[BATCH * HID], d_hb1[BATCH * HID];
__device__ float d_cd[BATCH * HID];
__device__ bf16  d_ebuf[BATCH * HID];
__device__ bf16  d_ctx[BATCH * HID];
__device__ bf16  d_inp[BATCH * HID];
__device__ float d_logits[(size_t)BATCH * VOCAB];
__device__ float d_benc[G4], d_bdec[G4];
__device__ float d_pm[BATCH * 512], d_ps[BATCH * 512];
__device__ int   d_pa[BATCH * 512];
__device__ float d_lse[BATCH];

// flag-based barriers
__device__ volatile unsigned d_arr[GRID];
__device__ volatile unsigned d_rel;
__device__ volatile unsigned d_arrE[T_ENC];
__device__ volatile unsigned d_relE;

__device__ bf16 d_attnT[SEQL * 2 * HID];              // attn_w transposed: [l][k]

// weights: [tile][k][64] (enc/dec gate-interleaved cols)
__device__ bf16 d_Wenc[(size_t)T_ENC * (EMBED + HID) * 64];
__device__ bf16 d_Wdec[(size_t)T_DEC * (2 * HID) * 64];
__device__ bf16 d_Wcmb[(size_t)T_CMB * (2 * HID) * 64];
__device__ bf16 d_Wout[(size_t)T_OUT * HID * 64];

__device__ __forceinline__ float sigm(float x) { return 1.f / (1.f + __expf(-x)); }

__device__ __forceinline__ float dot8(uint4 ua, uint4 uw) {
    float s = 0.f;
    const unsigned* a = (const unsigned*)&ua;
    const unsigned* w = (const unsigned*)&uw;
    #pragma unroll
    for (int j = 0; j < 4; j++) {
        float2 fa = __bfloat1622float2(*(const __nv_bfloat162*)&a[j]);
        float2 fw = __bfloat1622float2(*(const __nv_bfloat162*)&w[j]);
        s += fa.x * fw.x + fa.y * fw.y;
    }
    return s;
}

// ---------------- cp.async helpers ----------------
__device__ __forceinline__ void cp_async16(bf16* smem_dst, const bf16* gmem_src) {
    unsigned d = (unsigned)__cvta_generic_to_shared(smem_dst);
    asm volatile("cp.async.cg.shared.global [%0], [%1], 16;\n" :: "r"(d), "l"(gmem_src));
}
__device__ __forceinline__ void cp_commit() { asm volatile("cp.async.commit_group;\n"); }
template<int N>
__device__ __forceinline__ void cp_wait() { asm volatile("cp.async.wait_group %0;\n" :: "n"(N)); }
__device__ __forceinline__ void named_bar(int id) {
    asm volatile("bar.sync %0, 256;" :: "r"(id) : "memory");
}

// ---------------- flag-based barrier ----------------
__device__ __forceinline__ void sw_barrier(volatile unsigned* arr, volatile unsigned* rel,
                                           unsigned& gen, int nblk) {
    const unsigned target = gen + 1u;
    __threadfence();
    __syncthreads();
    if (threadIdx.x == 0) arr[blockIdx.x] = target;
    if (blockIdx.x == 0) {
        if ((int)threadIdx.x < nblk) {
            int it = 0;
            while (arr[threadIdx.x] < target) { if (++it > 128) __nanosleep(32); }
        }
        __syncthreads();
        __threadfence();
        if (threadIdx.x == 0) *rel = target;
    }
    if (threadIdx.x == 0) {
        int it = 0;
        while (*rel < target) { if (++it > 128) __nanosleep(32); }
        __threadfence();
    }
    gen = target;
    __syncthreads();
}

// ---------------- A staging ----------------
template<int K1, int K2>
__device__ __forceinline__ void stage_A(bf16* sA, const bf16* __restrict__ A1,
                                        const bf16* __restrict__ A2) {
    constexpr int K = K1 + K2;
    constexpr int tot = 32 * K / 8;
    for (int i = threadIdx.x; i < tot; i += TPB) {
        int m = i / (K / 8);
        int k = (i - m * (K / 8)) * 8;
        const bf16* s = (K2 == 0 || k < K1) ? (A1 + m * K1 + k) : (A2 + m * K2 + (k - K1));
        *(uint4*)(sA + m * (K + PAD) + k) = *(const uint4*)s;
    }
    __syncthreads();
}

// ---------------- GEMM: 16 warps, 2-way K-split ----------------
// warp w: mh=w&1 (16 rows), nq=(w>>1)&3 (16 cols), ks=w>>3 (K half).
// ks-group (8 warps) cooperatively streams its K/2 chunks through 2 slots,
// synced by named barrier 1+ks. Partials go to sC slab[ks]; epilogue sums.
template<int K>
__device__ __forceinline__ void gemm_tile(const bf16* sA, const bf16* __restrict__ Bt,
                                          float* sC, bf16* sB) {
    constexpr int LDA = K + PAD;
    constexpr int NC2 = K / CH / 2;        // chunks per group
    const int w   = threadIdx.x >> 5;
    const int lane = threadIdx.x & 31;
    const int mh = w & 1, nq = (w >> 1) & 3, ks = w >> 3;
    const int wg = w & 7;                  // warp index within group

    // per-warp share of a chunk copy: rows [wg*16, wg*16+16), 64 cols
    auto copy_chunk = [&](int cc, int slot) {
        const bf16* src = Bt + ((size_t)(ks * NC2 + cc) * CH + wg * 16) * 64;
        bf16* dst = sB + slot * SLOTSZ + wg * 16 * BLD;
        #pragma unroll
        for (int i = 0; i < 4; i++) {
            int seg = lane + i * 32;           // 128 segs of 16B
            int r = seg >> 3, cq = seg & 7;
            cp_async16(dst + r * BLD + cq * 8, src + r * 64 + cq * 8);
        }
        cp_commit();
    };

    copy_chunk(0, ks * 2);

    wmma::fragment<wmma::matrix_a, 16, 16, 16, bf16, wmma::row_major> fa;
    wmma::fragment<wmma::matrix_b, 16, 16, 16, bf16, wmma::row_major> fb;
    wmma::fragment<wmma::accumulator, 16, 16, 16, float> acc0, acc1;
    wmma::fill_fragment(acc0, 0.f);
    wmma::fill_fragment(acc1, 0.f);

    for (int cc = 0; cc < NC2; cc++) {
        cp_wait<0>();                      // my copies for chunk cc landed
        named_bar(1 + ks);                 // group: chunk cc visible; prior slot free
        if (cc + 1 < NC2) copy_chunk(cc + 1, ks * 2 + ((cc + 1) & 1));
        const bf16* bst = sB + (ks * 2 + (cc & 1)) * SLOTSZ + nq * 16;
        const bf16* ast = sA + (mh * 16) * LDA + (ks * NC2 + cc) * CH;
        #pragma unroll
        for (int kk = 0; kk < CH / 16; kk++) {
            wmma::load_matrix_sync(fa, ast + kk * 16, LDA);
            wmma::load_matrix_sync(fb, bst + kk * 16 * BLD, BLD);
            if (kk & 1) wmma::mma_sync(acc1, fa, fb, acc1);
            else        wmma::mma_sync(acc0, fa, fb, acc0);
        }
    }
    #pragma unroll
    for (int i = 0; i < acc0.num_elements; i++) acc0.x[i] += acc1.x[i];
    wmma::store_matrix_sync(sC + ks * 2048 + mh * 16 * 64 + nq * 16, acc0, 64,
                            wmma::mem_row_major);
    __syncthreads();                       // both slabs complete for epilogue
}

// ---------------- LSTM cell epilogue (sums 2 k-slabs) ----------------
__device__ __forceinline__ void cell_epi(const float* sC, const float* bias, int n0,
                                         float* cbuf, bf16* hb, bf16* enc_out, int t) {
    int i = threadIdx.x;                   // BATCH*16 = 512 exactly
    int m = i >> 4, dd = i & 15, cb = dd * 4;
    float g0 = sC[m * 64 + cb + 0] + sC[2048 + m * 64 + cb + 0] + bias[n0 + cb + 0];
    float g1 = sC[m * 64 + cb + 1] + sC[2048 + m * 64 + cb + 1] + bias[n0 + cb + 1];
    float g2 = sC[m * 64 + cb + 2] + sC[2048 + m * 64 + cb + 2] + bias[n0 + cb + 2];
    float g3 = sC[m * 64 + cb + 3] + sC[2048 + m * 64 + cb + 3] + bias[n0 + cb + 3];
    float gi = sigm(g0), gf = sigm(g1), gg = tanhf(g2), go = sigm(g3);
    int d = (n0 >> 2) + dd;
    int idx = m * HID + d;
    float c = gf * cbuf[idx] + gi * gg;
    float h = go * tanhf(c);
    cbuf[idx] = c;
    bf16 hb16 = __float2bfloat16(h);
    hb[idx] = hb16;
    if (enc_out) enc_out[((size_t)m * SEQL + t) * HID + d] = hb16;
    __syncthreads();
}

// ---------------- out-projection epilogue ----------------
__device__ __forceinline__ void epi_out(const float* sC, const float* __restrict__ out_b, int tile) {
    const int tid = threadIdx.x;
    const int r = tid >> 4, j0 = (tid & 15) * 4, n0 = tile * 64;
    float v[4];
    float pm = -INFINITY; int pa = 0;
    #pragma unroll
    for (int j = 0; j < 4; j++) {
        float x = sC[r * 64 + j0 + j] + sC[2048 + r * 64 + j0 + j] + out_b[n0 + j0 + j];
        v[j] = x;
        if (x > pm) { pm = x; pa = n0 + j0 + j; }
    }
    *(float4*)(d_logits + (size_t)r * VOCAB + n0 + j0) = make_float4(v[0], v[1], v[2], v[3]);
    float ps = 0.f;
    #pragma unroll
    for (int j = 0; j < 4; j++) ps += __expf(v[j] - pm);
    #pragma unroll
    for (int o = 8; o > 0; o >>= 1) {      // merge across 16-lane group (one row)
        float om = __shfl_xor_sync(0xffffffffu, pm, o);
        float os = __shfl_xor_sync(0xffffffffu, ps, o);
        int   oa = __shfl_xor_sync(0xffffffffu, pa, o);
        if (om > pm) { ps = ps * __expf(pm - om) + os; pm = om; pa = oa; }
        else if (om == pm) { ps += os; if (oa < pa) pa = oa; }
        else ps += os * __expf(om - pm);
    }
    if ((tid & 15) == 0) {
        d_pm[r * 512 + tile] = pm;
        d_ps[r * 512 + tile] = ps;
        d_pa[r * 512 + tile] = pa;
    }
    __syncthreads();
}

// ---------------- attention (TPB=512 layout) ----------------
__device__ void attn_phase(int b, const float* __restrict__ attn_b,
                           const bf16* __restrict__ hb, float* scratch) {
    float* aw = scratch;   // 64 floats
    const int tid = threadIdx.x;
    const int l = tid >> 3, part = tid & 7;        // 8 parts x 256 elems
    const bf16* e = d_ebuf + b * HID;
    const bf16* h = hb + b * HID;
    const uint4* wrow = (const uint4*)(d_attnT + (size_t)l * 2 * HID + part * 256);
    const uint4* av = (const uint4*)((part < 4) ? (e + part * 256) : (h + (part - 4) * 256));
    float s = 0.f;
    #pragma unroll 8
    for (int i = 0; i < 32; i++) s += dot8(av[i], wrow[i]);
    s += __shfl_xor_sync(0xffffffffu, s, 1);
    s += __shfl_xor_sync(0xffffffffu, s, 2);
    s += __shfl_xor_sync(0xffffffffu, s, 4);
    if (part == 0) aw[l] = s + attn_b[l];
    __syncthreads();
    if (tid == 0) {
        float mx = -INFINITY;
        for (int j = 0; j < SEQL; j++) mx = fmaxf(mx, aw[j]);
        float sum = 0.f;
        for (int j = 0; j < SEQL; j++) { float ev = __expf(aw[j] - mx); aw[j] = ev; sum += ev; }
        float inv = 1.f / sum;
        for (int j = 0; j < SEQL; j++) aw[j] *= inv;
    }
    __syncthreads();
    const bf16* eo = d_enc_outs + (size_t)b * SEQL * HID;
    const int d2 = tid * 2;                        // 512 threads x 2 cols
    float c0 = 0.f, c1 = 0.f;
    #pragma unroll 8
    for (int ll = 0; ll < SEQL; ll++) {
        float a = aw[ll];
        unsigned u = *(const unsigned*)(eo + (size_t)ll * HID + d2);
        float2 p = __bfloat1622float2(*(const __nv_bfloat162*)&u);
        c0 += a * p.x; c1 += a * p.y;
    }
    __nv_bfloat162 o = __floats2bfloat162_rn(c0, c1);
    *(unsigned*)(d_ctx + b * HID + d2) = *(unsigned*)&o;
    __syncthreads();
}

// ---------------- reduce partials -> lse, argmax, gather embedding ----------------
__device__ void reduce_phase(int b, const float* __restrict__ dec_embed, float* scratch) {
    const int tid = threadIdx.x;
    float* smax = scratch;
    float* ssum = scratch + 512;
    int*   sarg = (int*)(scratch + 1024);
    int*   stok = (int*)(scratch + 1536);
    float pm = -INFINITY, ps = 0.f; int pa = 0;
    for (int t = tid; t < T_OUT; t += TPB) {
        float om = d_pm[b * 512 + t], os = d_ps[b * 512 + t];
        int oa = d_pa[b * 512 + t];
        if (om > pm) { ps = ps * __expf(pm - om) + os; pm = om; pa = oa; }
        else if (om == pm) { ps += os; if (oa < pa) pa = oa; }
        else ps += os * __expf(om - pm);
    }
    smax[tid] = pm; ssum[tid] = ps; sarg[tid] = pa;
    __syncthreads();
    for (int st = 256; st > 0; st >>= 1) {
        if (tid < st) {
            float om = smax[tid + st], os = ssum[tid + st]; int oa = sarg[tid + st];
            float cm = smax[tid],      cs = ssum[tid];      int ca = sarg[tid];
            if (om > cm) { cs = cs * __expf(cm - om) + os; cm = om; ca = oa; }
            else if (om == cm) { cs += os; if (oa < ca) ca = oa; }
            else cs += os * __expf(om - cm);
            smax[tid] = cm; ssum[tid] = cs; sarg[tid] = ca;
        }
        __syncthreads();
    }
    if (tid == 0) { d_lse[b] = smax[0] + __logf(ssum[0]); stok[0] = sarg[0]; }
    __syncthreads();
    int token = stok[0];
    for (int d = tid; d < HID; d += TPB)
        d_ebuf[b * HID + d] = __float2bfloat16(dec_embed[(size_t)token * HID + d]);
    __syncthreads();
}

// ---------------- distributed log-p write ----------------
__device__ void fixup_logp(int step, float* __restrict__ out, int bfirst, int nblocks) {
    int lb = blockIdx.x - bfirst;
    const int tot = BATCH * (VOCAB / 4);
    for (int i = lb * TPB + threadIdx.x; i < tot; i += nblocks * TPB) {
        int b = i / (VOCAB / 4);
        int q = i - b * (VOCAB / 4);
        float4 f = ((const float4*)(d_logits + (size_t)b * VOCAB))[q];
        float lse = d_lse[b];
        f.x -= lse; f.y -= lse; f.z -= lse; f.w -= lse;
        ((float4*)(out + ((size_t)b * SEQL + step) * VOCAB))[q] = f;
    }
}

// ---------------- persistent kernel ----------------
__global__ __launch_bounds__(TPB, 1) void seq_kernel(
    const float* __restrict__ attn_b,
    const float* __restrict__ comb_b, const float* __restrict__ out_b,
    const float* __restrict__ dec_embed, float* __restrict__ out)
{
    extern __shared__ unsigned char dynmem[];
    bf16*  sA = (bf16*)dynmem;
    bf16*  sB = (bf16*)(dynmem + SA_BYTES);
    float* sC = (float*)(dynmem + SA_BYTES + SB_BYTES);
    float* scratch = (float*)sA;
    unsigned gen = 0, gen_enc = 0;
    const int bid = blockIdx.x;

    // ---- encoder: blocks 0-63 ----
    if (bid < T_ENC) {
        for (int t = 0; t < SEQL; t++) {
            const bf16* hr = (t & 1) ? d_gb1 : d_gb0;
            bf16*       hw = (t & 1) ? d_gb0 : d_gb1;
            stage_A<EMBED, HID>(sA, d_Eenc + (size_t)t * BATCH * EMBED, hr);
            gemm_tile<EMBED + HID>(sA, d_Wenc + (size_t)bid * (EMBED + HID) * 64, sC, sB);
            cell_epi(sC, d_benc, bid * 64, d_ce, hw, d_enc_outs, t);
            sw_barrier(d_arrE, &d_relE, gen_enc, T_ENC);
        }
    }
    sw_barrier(d_arr, &d_rel, gen, GRID);

    // ---- decoder ----
    for (int s = 0; s < SEQL; s++) {
        const bf16* hr = (s & 1) ? d_hb1 : d_hb0;
        bf16*       hw = (s & 1) ? d_hb0 : d_hb1;
        // phase EA: reduce(s-1) + attention(s) on blocks 0-31
        if (bid < BATCH) {
            if (s > 0) reduce_phase(bid, dec_embed, scratch);
            attn_phase(bid, attn_b, hr, scratch);
        }
        sw_barrier(d_arr, &d_rel, gen, GRID);
        // phase B: combine (0-15) || logp fixup of step s-1 (16-147)
        if (bid < T_CMB) {
            stage_A<HID, HID>(sA, d_ebuf, d_ctx);
            gemm_tile<2 * HID>(sA, d_Wcmb + (size_t)bid * (2 * HID) * 64, sC, sB);
            int n0 = bid * 64;
            for (int i = threadIdx.x; i < BATCH * 64; i += TPB) {
                int m = i >> 6, j = i & 63;
                float v = sC[m * 64 + j] + sC[2048 + m * 64 + j] + comb_b[n0 + j];
                d_inp[m * HID + n0 + j] = __float2bfloat16(fmaxf(v, 0.f));
            }
            __syncthreads();
        } else if (s > 0) {
            fixup_logp(s - 1, out, T_CMB, GRID - T_CMB);
        }
        sw_barrier(d_arr, &d_rel, gen, GRID);
        // phase C: decoder LSTM gates + cell
        if (bid < T_DEC) {
            stage_A<HID, HID>(sA, d_inp, hr);
            gemm_tile<2 * HID>(sA, d_Wdec + (size_t)bid * (2 * HID) * 64, sC, sB);
            cell_epi(sC, d_bdec, bid * 64, d_cd, hw, nullptr, 0);
        }
        sw_barrier(d_arr, &d_rel, gen, GRID);
        // phase D: out projection, balanced
        stage_A<HID, 0>(sA, hw, nullptr);
        int t0, nt;
        if (bid < 92) { t0 = bid * 3;              nt = 3; }
        else          { t0 = 276 + (bid - 92) * 4; nt = 4; }
        for (int i = 0; i < nt; i++) {
            int tile = t0 + i;
            gemm_tile<HID>(sA, d_Wout + (size_t)tile * HID * 64, sC, sB);
            epi_out(sC, out_b, tile);
        }
        sw_barrier(d_arr, &d_rel, gen, GRID);
    }
    // tail
    if (bid < BATCH) reduce_phase(bid, dec_embed, scratch);
    sw_barrier(d_arr, &d_rel, gen, GRID);
    fixup_logp(SEQL - 1, out, 0, GRID);
}

// ---------------- prep: [tile][k][64] weight layout ----------------
__global__ void prep_kernel(
    const int* __restrict__ x, const float* __restrict__ enc_embed,
    const float* __restrict__ enc_wx, const float* __restrict__ enc_wh,
    const float* __restrict__ enc_b, const float* __restrict__ dec_embed,
    const float* __restrict__ attn_w, const float* __restrict__ comb_w,
    const float* __restrict__ dec_wx, const float* __restrict__ dec_wh,
    const float* __restrict__ dec_b, const float* __restrict__ out_w)
{
    const size_t gs = (size_t)gridDim.x * blockDim.x;
    const size_t g0 = (size_t)blockIdx.x * blockDim.x + threadIdx.x;

    for (size_t i = g0; i < (size_t)T_ENC * 1536 * 64; i += gs) {
        int tile = (int)(i / 98304); int r = (int)(i % 98304);
        int k = r >> 6, j = r & 63;
        int c = tile * 64 + j, d = c >> 2, g = c & 3, sc = g * HID + d;
        float v = (k < EMBED) ? enc_wx[(size_t)k * G4 + sc]
                              : enc_wh[(size_t)(k - EMBED) * G4 + sc];
        d_Wenc[i] = __float2bfloat16(v);
    }
    for (size_t i = g0; i < (size_t)T_DEC * 2048 * 64; i += gs) {
        int tile = (int)(i / 131072); int r = (int)(i % 131072);
        int k = r >> 6, j = r & 63;
        int c = tile * 64 + j, d = c >> 2, g = c & 3, sc = g * HID + d;
        float v = (k < HID) ? dec_wx[(size_t)k * G4 + sc]
                            : dec_wh[(size_t)(k - HID) * G4 + sc];
        d_Wdec[i] = __float2bfloat16(v);
    }
    for (size_t i = g0; i < (size_t)T_CMB * 2048 * 64; i += gs) {
        int tile = (int)(i / 131072); int r = (int)(i % 131072);
        int k = r >> 6, j = r & 63;
        d_Wcmb[i] = __float2bfloat16(comb_w[(size_t)k * HID + tile * 64 + j]);
    }
    for (size_t i = g0; i < (size_t)T_OUT * HID * 64; i += gs) {
        int tile = (int)(i >> 16); int r = (int)(i & 65535);
        int k = r >> 6, j = r & 63;
        d_Wout[i] = __float2bfloat16(out_w[(size_t)k * VOCAB + tile * 64 + j]);
    }
    for (size_t i = g0; i < (size_t)SEQL * 2 * HID; i += gs) {
        int l = (int)(i >> 11), k = (int)(i & 2047);
        d_attnT[i] = __float2bfloat16(attn_w[(size_t)k * SEQL + l]);
    }
    for (size_t i = g0; i < G4; i += gs) {
        int d = (int)(i >> 2), g = (int)(i & 3);
        d_benc[i] = enc_b[g * HID + d];
        d_bdec[i] = dec_b[g * HID + d];
    }
    for (size_t i = g0; i < BATCH * HID; i += gs) {
        bf16 z = __float2bfloat16(0.f);
        d_gb0[i] = z; d_gb1[i] = z; d_ce[i] = 0.f;
        d_hb0[i] = z; d_hb1[i] = z; d_cd[i] = 0.f;
        d_ebuf[i] = __float2bfloat16(dec_embed[(size_t)127 * HID + (i % HID)]);
    }
    for (size_t i = g0; i < (size_t)SEQL * BATCH * EMBED; i += gs) {
        int t = (int)(i / (BATCH * EMBED));
        int r = (int)(i % (BATCH * EMBED));
        int b = r / EMBED, d = r % EMBED;
        int tok = x[b * SEQL + t];
        d_Eenc[i] = __float2bfloat16(enc_embed[(size_t)tok * EMBED + d]);
    }
    if (g0 < GRID) d_arr[g0] = 0u;
    if (g0 < T_ENC) d_arrE[g0] = 0u;
    if (g0 == 0) { d_rel = 0u; d_relE = 0u; }
}

// ---------------- host launch ----------------
extern "C" void kernel_launch(void* const* d_in, const int* in_sizes, int n_in,
                              void* d_out, int out_size) {
    (void)in_sizes; (void)n_in; (void)out_size;
    const int*   x         = (const int*)d_in[0];
    const float* enc_embed = (const float*)d_in[1];
    const float* enc_wx    = (const float*)d_in[2];
    const float* enc_wh    = (const float*)d_in[3];
    const float* enc_b     = (const float*)d_in[4];
    const float* dec_embed = (const float*)d_in[5];
    const float* attn_w    = (const float*)d_in[6];
    const float* attn_b    = (const float*)d_in[7];
    const float* comb_w    = (const float*)d_in[8];
    const float* comb_b    = (const float*)d_in[9];
    const float* dec_wx    = (const float*)d_in[10];
    const float* dec_wh    = (const float*)d_in[11];
    const float* dec_b     = (const float*)d_in[12];
    const float* out_w     = (const float*)d_in[13];
    const float* out_b     = (const float*)d_in[14];
    float* out = (float*)d_out;

    cudaFuncSetAttribute(seq_kernel, cudaFuncAttributeMaxDynamicSharedMemorySize, SMEM_DYN);

    prep_kernel<<<2048, 256>>>(x, enc_embed, enc_wx, enc_wh, enc_b, dec_embed,
                               attn_w, comb_w, dec_wx, dec_wh, dec_b, out_w);
    seq_kernel<<<GRID, TPB, SMEM_DYN>>>(attn_b, comb_b, out_b, dec_embed, out);
}